// round 1
// baseline (speedup 1.0000x reference)
#include <cuda_runtime.h>
#include <cuda_bf16.h>
#include <cstdint>

// Problem constants
#define EMB   1024
#define HID   4096
#define NHEADS 16
#define DK    64
#define BATCH 2
#define SEQ   2048
#define ROWS  (BATCH*SEQ)        // 4096
#define LNEPS 1e-6f

// ---------------- scratch (device globals; no allocation) ----------------
__device__ float g_ln  [ROWS*EMB];            // 16 MB
__device__ float g_q   [BATCH*NHEADS*SEQ*DK]; // 16 MB
__device__ float g_k   [BATCH*NHEADS*SEQ*DK];
__device__ float g_v   [BATCH*NHEADS*SEQ*DK];
__device__ float g_attn[ROWS*EMB];
__device__ float g_h   [ROWS*EMB];
__device__ float g_ff  [ROWS*HID];            // 64 MB

// ---------------- LayerNorm (Bessel variance, /(std+eps)) ----------------
__global__ void ln_kernel(const float* __restrict__ x, float* __restrict__ y,
                          const float* __restrict__ alpha, const float* __restrict__ beta) {
    __shared__ float red[8];
    int row = blockIdx.x;
    int t = threadIdx.x;                      // 256 threads, 4 elems each
    const float* xr = x + (size_t)row * EMB;
    float v[4];
#pragma unroll
    for (int i = 0; i < 4; i++) v[i] = xr[t + 256 * i];

    // mean
    float s = v[0] + v[1] + v[2] + v[3];
#pragma unroll
    for (int o = 16; o > 0; o >>= 1) s += __shfl_xor_sync(0xffffffffu, s, o);
    if ((t & 31) == 0) red[t >> 5] = s;
    __syncthreads();
    float tot = 0.f;
#pragma unroll
    for (int i = 0; i < 8; i++) tot += red[i];
    float mean = tot * (1.0f / EMB);
    __syncthreads();

    // variance (Bessel)
    float sq = 0.f;
#pragma unroll
    for (int i = 0; i < 4; i++) { float d = v[i] - mean; sq += d * d; }
#pragma unroll
    for (int o = 16; o > 0; o >>= 1) sq += __shfl_xor_sync(0xffffffffu, sq, o);
    if ((t & 31) == 0) red[t >> 5] = sq;
    __syncthreads();
    float sqt = 0.f;
#pragma unroll
    for (int i = 0; i < 8; i++) sqt += red[i];
    float var = sqt * (1.0f / (EMB - 1));
    float stdv = sqrtf(var);
    float scale = alpha[0] / (stdv + LNEPS);
    float bias = beta[0];

    float* yr = y + (size_t)row * EMB;
#pragma unroll
    for (int i = 0; i < 4; i++) yr[t + 256 * i] = scale * (v[i] - mean) + bias;
}

// ---------------- SGEMM 128x128x8, 256 threads, 8x8 per thread ----------------
enum { EPI_NONE = 0, EPI_HEADS = 1, EPI_RES = 2, EPI_BIAS_RELU = 3, EPI_BIAS_RES = 4 };

template <int EPI>
__global__ __launch_bounds__(256, 2)
void sgemm_kernel(const float* __restrict__ A, const float* __restrict__ B,
                  float* __restrict__ C, int M, int N, int K,
                  const float* __restrict__ bias, const float* __restrict__ res) {
    __shared__ float As[8][128];
    __shared__ float Bs[8][128];

    int tid = threadIdx.x;
    int bx = blockIdx.x, by = blockIdx.y;
    int tx = tid & 15, ty = tid >> 4;

    int aRow = tid >> 1, aCol = (tid & 1) * 4;
    int bRow = tid >> 5, bCol = (tid & 31) * 4;

    const float* Ag = A + (size_t)(by * 128 + aRow) * K + aCol;
    const float* Bg = B + (size_t)bRow * N + (size_t)bx * 128 + bCol;

    float acc[8][8];
#pragma unroll
    for (int i = 0; i < 8; i++)
#pragma unroll
        for (int j = 0; j < 8; j++) acc[i][j] = 0.f;

    for (int k0 = 0; k0 < K; k0 += 8) {
        float4 av = *(const float4*)(Ag + k0);
        float4 bv = *(const float4*)(Bg + (size_t)k0 * N);
        __syncthreads();
        As[aCol + 0][aRow] = av.x;
        As[aCol + 1][aRow] = av.y;
        As[aCol + 2][aRow] = av.z;
        As[aCol + 3][aRow] = av.w;
        *(float4*)&Bs[bRow][bCol] = bv;
        __syncthreads();
#pragma unroll
        for (int k = 0; k < 8; k++) {
            float a[8], b[8];
            *(float4*)(a)     = *(const float4*)&As[k][ty * 8];
            *(float4*)(a + 4) = *(const float4*)&As[k][ty * 8 + 4];
            *(float4*)(b)     = *(const float4*)&Bs[k][tx * 8];
            *(float4*)(b + 4) = *(const float4*)&Bs[k][tx * 8 + 4];
#pragma unroll
            for (int i = 0; i < 8; i++)
#pragma unroll
                for (int j = 0; j < 8; j++) acc[i][j] += a[i] * b[j];
        }
    }

#pragma unroll
    for (int i = 0; i < 8; i++) {
        int row = by * 128 + ty * 8 + i;
#pragma unroll
        for (int j = 0; j < 8; j++) {
            int col = bx * 128 + tx * 8 + j;
            float v = acc[i][j];
            if (EPI == EPI_BIAS_RELU || EPI == EPI_BIAS_RES) v += bias[col];
            if (EPI == EPI_BIAS_RELU) v = fmaxf(v, 0.f);
            if (EPI == EPI_RES || EPI == EPI_BIAS_RES) v += res[(size_t)row * N + col];
            if (EPI == EPI_HEADS) {
                // row = b*SEQ + s ; col = h*DK + d  ->  [B,H,S,DK]
                int b_ = row >> 11, s_ = row & (SEQ - 1);
                int h_ = col >> 6, d_ = col & (DK - 1);
                C[(((size_t)b_ * NHEADS + h_) * SEQ + s_) * DK + d_] = v;
            } else {
                C[(size_t)row * N + col] = v;
            }
        }
    }
}

// ---------------- flash attention (fp32, 64q x 32k tiles) ----------------
__global__ __launch_bounds__(256, 2)
void attn_kernel(const float* __restrict__ Q, const float* __restrict__ K,
                 const float* __restrict__ V, const int* __restrict__ mask,
                 float* __restrict__ out) {
    __shared__ float Qs[64][65];
    __shared__ float Ks[32][65];
    __shared__ float Vs[32][65];
    __shared__ float Ps[64][33];
    __shared__ int Ms[32];

    int qt = blockIdx.x;          // 0..31 query tiles
    int bh = blockIdx.y;          // 0..31 (b*16+h)
    int b = bh >> 4;
    int t = threadIdx.x;
    int q = t >> 2, sub = t & 3;

    const float* Qb = Q + ((size_t)bh * SEQ + qt * 64) * DK;
    const float* Kb = K + (size_t)bh * SEQ * DK;
    const float* Vb = V + (size_t)bh * SEQ * DK;

    for (int idx = t; idx < 64 * 64; idx += 256) Qs[idx >> 6][idx & 63] = Qb[idx];

    float m = -1e30f, l = 0.f;
    float O[16];
#pragma unroll
    for (int i = 0; i < 16; i++) O[i] = 0.f;

    for (int k0 = 0; k0 < SEQ; k0 += 32) {
        __syncthreads();   // previous iter done with Ks/Vs/Ps
        for (int idx = t; idx < 32 * 64; idx += 256) {
            int r = idx >> 6, c = idx & 63;
            Ks[r][c] = Kb[(size_t)(k0 + r) * DK + c];
            Vs[r][c] = Vb[(size_t)(k0 + r) * DK + c];
        }
        if (t < 32) Ms[t] = mask[b * SEQ + k0 + t];
        __syncthreads();

        float sc[8];
#pragma unroll
        for (int kk = 0; kk < 8; kk++) sc[kk] = 0.f;
#pragma unroll
        for (int d = 0; d < 64; d++) {
            float qv = Qs[q][d];
#pragma unroll
            for (int kk = 0; kk < 8; kk++) sc[kk] += qv * Ks[sub * 8 + kk][d];
        }
        float rmax = -1e30f;
#pragma unroll
        for (int kk = 0; kk < 8; kk++) {
            sc[kk] = Ms[sub * 8 + kk] ? sc[kk] * 0.125f : -1e30f;
            rmax = fmaxf(rmax, sc[kk]);
        }
        rmax = fmaxf(rmax, __shfl_xor_sync(0xffffffffu, rmax, 1));
        rmax = fmaxf(rmax, __shfl_xor_sync(0xffffffffu, rmax, 2));
        float mn = fmaxf(m, rmax);
        float rsum = 0.f;
#pragma unroll
        for (int kk = 0; kk < 8; kk++) { sc[kk] = __expf(sc[kk] - mn); rsum += sc[kk]; }
        rsum += __shfl_xor_sync(0xffffffffu, rsum, 1);
        rsum += __shfl_xor_sync(0xffffffffu, rsum, 2);
        float al = __expf(m - mn);
        l = l * al + rsum;
        m = mn;
#pragma unroll
        for (int i = 0; i < 16; i++) O[i] *= al;
#pragma unroll
        for (int kk = 0; kk < 8; kk++) Ps[q][sub * 8 + kk] = sc[kk];
        __syncthreads();
#pragma unroll
        for (int k = 0; k < 32; k++) {
            float pv = Ps[q][k];
#pragma unroll
            for (int i = 0; i < 16; i++) O[i] += pv * Vs[k][sub * 16 + i];
        }
    }

    float inv = 1.f / l;
    int s = qt * 64 + q;
    int h = bh & 15;
    float* op = out + ((size_t)b * SEQ + s) * EMB + h * DK + sub * 16;
#pragma unroll
    for (int i = 0; i < 16; i++) op[i] = O[i] * inv;
}

// ---------------- launch ----------------
extern "C" void kernel_launch(void* const* d_in, const int* in_sizes, int n_in,
                              void* d_out, int out_size) {
    const float* x    = (const float*)d_in[0];
    const int*   mask = (const int*)  d_in[1];
    const float* wq   = (const float*)d_in[2];
    const float* wk   = (const float*)d_in[3];
    const float* wv   = (const float*)d_in[4];
    const float* wo   = (const float*)d_in[5];
    const float* ff1w = (const float*)d_in[6];
    const float* ff1b = (const float*)d_in[7];
    const float* ff2w = (const float*)d_in[8];
    const float* ff2b = (const float*)d_in[9];
    const float* ln1a = (const float*)d_in[10];
    const float* ln1b = (const float*)d_in[11];
    const float* ln2a = (const float*)d_in[12];
    const float* ln2b = (const float*)d_in[13];
    float* out = (float*)d_out;

    float *t_ln, *qb, *kb, *vb, *ab, *hb, *fb;
    cudaGetSymbolAddress((void**)&t_ln, g_ln);
    cudaGetSymbolAddress((void**)&qb, g_q);
    cudaGetSymbolAddress((void**)&kb, g_k);
    cudaGetSymbolAddress((void**)&vb, g_v);
    cudaGetSymbolAddress((void**)&ab, g_attn);
    cudaGetSymbolAddress((void**)&hb, g_h);
    cudaGetSymbolAddress((void**)&fb, g_ff);

    dim3 gP(EMB / 128, ROWS / 128);   // (8,32)  N=1024 GEMMs
    dim3 gF(HID / 128, ROWS / 128);   // (32,32) N=4096 GEMM

    // 1) LN1
    ln_kernel<<<ROWS, 256>>>(x, t_ln, ln1a, ln1b);
    // 2) Q/K/V projections (head-split output)
    sgemm_kernel<EPI_HEADS><<<gP, 256>>>(t_ln, wq, qb, ROWS, EMB, EMB, nullptr, nullptr);
    sgemm_kernel<EPI_HEADS><<<gP, 256>>>(t_ln, wk, kb, ROWS, EMB, EMB, nullptr, nullptr);
    sgemm_kernel<EPI_HEADS><<<gP, 256>>>(t_ln, wv, vb, ROWS, EMB, EMB, nullptr, nullptr);
    // 3) attention
    attn_kernel<<<dim3(SEQ / 64, BATCH * NHEADS), 256>>>(qb, kb, vb, mask, ab);
    // 4) output projection + residual x  -> h
    sgemm_kernel<EPI_RES><<<gP, 256>>>(ab, wo, hb, ROWS, EMB, EMB, nullptr, x);
    // 5) LN2
    ln_kernel<<<ROWS, 256>>>(hb, t_ln, ln2a, ln2b);
    // 6) FFN up + bias + relu
    sgemm_kernel<EPI_BIAS_RELU><<<gF, 256>>>(t_ln, ff1w, fb, ROWS, HID, EMB, ff1b, nullptr);
    // 7) FFN down + bias + residual h -> out
    sgemm_kernel<EPI_BIAS_RES><<<gP, 256>>>(fb, ff2w, out, ROWS, EMB, HID, ff2b, hb);
}

// round 3
// speedup vs baseline: 2.1756x; 2.1756x over previous
#include <cuda_runtime.h>
#include <cuda_bf16.h>
#include <cstdint>

#define EMB   1024
#define HID   4096
#define NHEADS 16
#define DK    64
#define BATCH 2
#define SEQ   2048
#define ROWS  (BATCH*SEQ)        // 4096
#define LNEPS 1e-6f

// ==================== scratch (device globals) ====================
__device__ float          g_q   [ROWS*EMB];
__device__ float          g_k   [ROWS*EMB];
__device__ float          g_v   [ROWS*EMB];
__device__ float          g_h   [ROWS*EMB];
__device__ __nv_bfloat16  g_lnh [ROWS*EMB];
__device__ __nv_bfloat16  g_lnl [ROWS*EMB];
__device__ __nv_bfloat16  g_ath [ROWS*EMB];
__device__ __nv_bfloat16  g_atl [ROWS*EMB];
__device__ __nv_bfloat16  g_ffh [ROWS*HID];
__device__ __nv_bfloat16  g_ffl [ROWS*HID];
// transposed split weights  [N x K]
__device__ __nv_bfloat16  g_wqh[EMB*EMB], g_wql[EMB*EMB];
__device__ __nv_bfloat16  g_wkh[EMB*EMB], g_wkl[EMB*EMB];
__device__ __nv_bfloat16  g_wvh[EMB*EMB], g_wvl[EMB*EMB];
__device__ __nv_bfloat16  g_woh[EMB*EMB], g_wol[EMB*EMB];
__device__ __nv_bfloat16  g_f1h[EMB*HID], g_f1l[EMB*HID];
__device__ __nv_bfloat16  g_f2h[EMB*HID], g_f2l[EMB*HID];

// ==================== baseline-PTX helpers (no 'a' features) ====================
__device__ __forceinline__ uint32_t smem_u32(const void* p) {
    uint32_t a;
    asm("{ .reg .u64 t; cvta.to.shared.u64 t, %1; cvt.u32.u64 %0, t; }" : "=r"(a) : "l"(p));
    return a;
}
__device__ __forceinline__ void cpa16(uint32_t dst, const void* src) {
    asm volatile("cp.async.cg.shared.global [%0], [%1], 16;" :: "r"(dst), "l"(src));
}
__device__ __forceinline__ void ldm4(uint32_t* r, uint32_t addr) {
    asm volatile("ldmatrix.sync.aligned.m8n8.x4.shared.b16 {%0,%1,%2,%3}, [%4];"
                 : "=r"(r[0]), "=r"(r[1]), "=r"(r[2]), "=r"(r[3]) : "r"(addr));
}
__device__ __forceinline__ void mma_bf16(float* d, const uint32_t* a, const uint32_t* b) {
    asm volatile("mma.sync.aligned.m16n8k16.row.col.f32.bf16.bf16.f32 "
                 "{%0,%1,%2,%3}, {%4,%5,%6,%7}, {%8,%9}, {%0,%1,%2,%3};"
                 : "+f"(d[0]), "+f"(d[1]), "+f"(d[2]), "+f"(d[3])
                 : "r"(a[0]), "r"(a[1]), "r"(a[2]), "r"(a[3]), "r"(b[0]), "r"(b[1]));
}

// ==================== split-transpose: W[K x N] fp32 -> T[N x K] bf16 hi/lo ====================
__global__ void splitT_kernel(const float* __restrict__ W,
                              __nv_bfloat16* __restrict__ Th,
                              __nv_bfloat16* __restrict__ Tl, int K, int N) {
    __shared__ float tile[32][33];
    int n0 = blockIdx.x * 32, k0 = blockIdx.y * 32;
    int tx = threadIdx.x, ty = threadIdx.y;       // 32 x 8
#pragma unroll
    for (int i = 0; i < 32; i += 8)
        tile[ty + i][tx] = W[(size_t)(k0 + ty + i) * N + n0 + tx];
    __syncthreads();
#pragma unroll
    for (int i = 0; i < 32; i += 8) {
        float v = tile[tx][ty + i];
        __nv_bfloat16 h = __float2bfloat16(v);
        float lo = v - __bfloat162float(h);
        size_t o = (size_t)(n0 + ty + i) * K + k0 + tx;
        Th[o] = h;
        Tl[o] = __float2bfloat16(lo);
    }
}

// ==================== LayerNorm -> bf16 hi/lo ====================
__global__ void ln_kernel(const float* __restrict__ x,
                          __nv_bfloat16* __restrict__ yh, __nv_bfloat16* __restrict__ yl,
                          const float* __restrict__ alpha, const float* __restrict__ beta) {
    __shared__ float red[8];
    int row = blockIdx.x;
    int t = threadIdx.x;
    const float* xr = x + (size_t)row * EMB;
    float v[4];
#pragma unroll
    for (int i = 0; i < 4; i++) v[i] = xr[t + 256 * i];
    float s = v[0] + v[1] + v[2] + v[3];
#pragma unroll
    for (int o = 16; o > 0; o >>= 1) s += __shfl_xor_sync(0xffffffffu, s, o);
    if ((t & 31) == 0) red[t >> 5] = s;
    __syncthreads();
    float tot = 0.f;
#pragma unroll
    for (int i = 0; i < 8; i++) tot += red[i];
    float mean = tot * (1.0f / EMB);
    __syncthreads();
    float sq = 0.f;
#pragma unroll
    for (int i = 0; i < 4; i++) { float d = v[i] - mean; sq += d * d; }
#pragma unroll
    for (int o = 16; o > 0; o >>= 1) sq += __shfl_xor_sync(0xffffffffu, sq, o);
    if ((t & 31) == 0) red[t >> 5] = sq;
    __syncthreads();
    float sqt = 0.f;
#pragma unroll
    for (int i = 0; i < 8; i++) sqt += red[i];
    float stdv = sqrtf(sqt * (1.0f / (EMB - 1)));
    float scale = alpha[0] / (stdv + LNEPS);
    float bias = beta[0];
#pragma unroll
    for (int i = 0; i < 4; i++) {
        float y = scale * (v[i] - mean) + bias;
        __nv_bfloat16 h = __float2bfloat16(y);
        size_t o = (size_t)row * EMB + t + 256 * i;
        yh[o] = h;
        yl[o] = __float2bfloat16(y - __bfloat162float(h));
    }
}

// ==================== mma.sync split-bf16 GEMM ====================
// C[4096 x N] = A[4096 x K] * B^T   (B stored [N x K], hi/lo pairs)
// CTA tile 128x128, BK=32 double-buffered via cp.async.
// 8 warps: warp (wm, wn) owns 64x32; mma m16n8k16; 3 split passes.
enum { EPI_HEADS = 1, EPI_RES = 2, EPI_BIAS_RELU_SPLIT = 3, EPI_BIAS_RES = 4 };

#define TSTRIDE   10240            // 128 rows * 80B (32 bf16 + 8 pad)
#define BUFSTRIDE (4*TSTRIDE)      // Ah, Al, Bh, Bl
#define MGEMM_SMEM (2*BUFSTRIDE)   // 81920 B

template <int EPI>
__global__ __launch_bounds__(256, 2)
void mgemm_kernel(const __nv_bfloat16* __restrict__ Ah, const __nv_bfloat16* __restrict__ Al,
                  const __nv_bfloat16* __restrict__ Bh, const __nv_bfloat16* __restrict__ Bl,
                  int K, int N,
                  float* __restrict__ C, const float* __restrict__ bias,
                  const float* __restrict__ res,
                  __nv_bfloat16* __restrict__ Ch, __nv_bfloat16* __restrict__ Cl) {
    extern __shared__ char sm[];
    const int tid = threadIdx.x;
    const int lane = tid & 31, wid = tid >> 5;
    const int wm = wid >> 2, wn = wid & 3;           // 2 x 4 warps
    const int bx = blockIdx.x, by = blockIdx.y;
    const uint32_t sb = smem_u32(sm);

    const __nv_bfloat16* gm[4] = {
        Ah + (size_t)(by * 128) * K, Al + (size_t)(by * 128) * K,
        Bh + (size_t)(bx * 128) * K, Bl + (size_t)(bx * 128) * K };

    float acc[4][4][4];
#pragma unroll
    for (int i = 0; i < 4; i++)
#pragma unroll
        for (int j = 0; j < 4; j++)
#pragma unroll
            for (int r = 0; r < 4; r++) acc[i][j][r] = 0.f;

    auto load_chunk = [&](int c, int buf) {
        const size_t koff = (size_t)c * 32;
#pragma unroll
        for (int tl = 0; tl < 4; tl++) {
#pragma unroll
            for (int i = 0; i < 2; i++) {
                int id = tid + 256 * i;
                int r = id >> 2, cc = id & 3;
                cpa16(sb + buf * BUFSTRIDE + tl * TSTRIDE + r * 80 + cc * 16,
                      gm[tl] + (size_t)r * K + koff + cc * 8);
            }
        }
    };

    const int nch = K >> 5;
    load_chunk(0, 0);
    asm volatile("cp.async.commit_group;" ::: "memory");

    for (int c = 0; c < nch; c++) {
        if (c + 1 < nch) {
            load_chunk(c + 1, (c + 1) & 1);
            asm volatile("cp.async.commit_group;" ::: "memory");
            asm volatile("cp.async.wait_group 1;" ::: "memory");
        } else {
            asm volatile("cp.async.wait_group 0;" ::: "memory");
        }
        __syncthreads();

        const uint32_t base = sb + (c & 1) * BUFSTRIDE;
        const char* bufc = sm + (c & 1) * BUFSTRIDE;
#pragma unroll
        for (int kk = 0; kk < 2; kk++) {
            const int kb = kk * 32;                  // byte offset of this k16
            // ---- A hi fragments via ldmatrix ----
            uint32_t ah[4][4], al4[4][4];
            const uint32_t arow = base + ((wm * 64 + (lane & 15)) * 80) + kb + ((lane >> 4) << 4);
#pragma unroll
            for (int mb = 0; mb < 4; mb++) ldm4(ah[mb], arow + mb * 16 * 80);
            // ---- B hi fragments via plain LDS.32 ----
            uint32_t bh[4][2], bl[4][2];
#pragma unroll
            for (int nb = 0; nb < 4; nb++) {
                const char* p = bufc + 2 * TSTRIDE
                              + (wn * 32 + nb * 8 + (lane >> 2)) * 80 + kb + (lane & 3) * 4;
                bh[nb][0] = *(const uint32_t*)p;
                bh[nb][1] = *(const uint32_t*)(p + 16);
            }
            // pass 1: hi * hi
#pragma unroll
            for (int mb = 0; mb < 4; mb++)
#pragma unroll
                for (int nb = 0; nb < 4; nb++) mma_bf16(acc[mb][nb], ah[mb], bh[nb]);
            // ---- A lo ----
#pragma unroll
            for (int mb = 0; mb < 4; mb++) ldm4(al4[mb], arow + TSTRIDE + mb * 16 * 80);
            // pass 2: lo * hi  (bh dead after)
#pragma unroll
            for (int mb = 0; mb < 4; mb++)
#pragma unroll
                for (int nb = 0; nb < 4; nb++) mma_bf16(acc[mb][nb], al4[mb], bh[nb]);
            // ---- B lo ----
#pragma unroll
            for (int nb = 0; nb < 4; nb++) {
                const char* p = bufc + 3 * TSTRIDE
                              + (wn * 32 + nb * 8 + (lane >> 2)) * 80 + kb + (lane & 3) * 4;
                bl[nb][0] = *(const uint32_t*)p;
                bl[nb][1] = *(const uint32_t*)(p + 16);
            }
            // pass 3: hi * lo
#pragma unroll
            for (int mb = 0; mb < 4; mb++)
#pragma unroll
                for (int nb = 0; nb < 4; nb++) mma_bf16(acc[mb][nb], ah[mb], bl[nb]);
        }
        __syncthreads();
    }

    // ==================== epilogue ====================
    const int g = lane >> 2, cb = (lane & 3) * 2;
#pragma unroll
    for (int mb = 0; mb < 4; mb++) {
#pragma unroll
        for (int hh = 0; hh < 2; hh++) {
            const int row = by * 128 + wm * 64 + mb * 16 + g + hh * 8;
#pragma unroll
            for (int nb = 0; nb < 4; nb++) {
                const int col = bx * 128 + wn * 32 + nb * 8 + cb;
                float v0 = acc[mb][nb][hh * 2 + 0];
                float v1 = acc[mb][nb][hh * 2 + 1];
                if (EPI == EPI_HEADS) {
                    int b_ = row >> 11, s_ = row & (SEQ - 1);
                    int h_ = col >> 6, d_ = col & (DK - 1);
                    float* dst = C + (((size_t)b_ * NHEADS + h_) * SEQ + s_) * DK + d_;
                    dst[0] = v0; dst[1] = v1;
                } else if (EPI == EPI_RES) {
                    size_t o = (size_t)row * N + col;
                    C[o]     = v0 + res[o];
                    C[o + 1] = v1 + res[o + 1];
                } else if (EPI == EPI_BIAS_RELU_SPLIT) {
                    v0 = fmaxf(v0 + bias[col], 0.f);
                    v1 = fmaxf(v1 + bias[col + 1], 0.f);
                    __nv_bfloat16 h0 = __float2bfloat16(v0);
                    __nv_bfloat16 h1 = __float2bfloat16(v1);
                    size_t o = (size_t)row * N + col;
                    Ch[o] = h0; Ch[o + 1] = h1;
                    Cl[o]     = __float2bfloat16(v0 - __bfloat162float(h0));
                    Cl[o + 1] = __float2bfloat16(v1 - __bfloat162float(h1));
                } else { // EPI_BIAS_RES
                    size_t o = (size_t)row * N + col;
                    C[o]     = v0 + bias[col]     + res[o];
                    C[o + 1] = v1 + bias[col + 1] + res[o + 1];
                }
            }
        }
    }
}

// ==================== flash attention (fp32, 128q x 128k, 8x8 blocks) ====================
#define ATT_QS 0
#define ATT_KS 8320
#define ATT_VS 16640
#define ATT_PS 25344
#define ATT_RM 41856
#define ATT_RL 41984
#define ATT_RA 42112
#define ATT_MS 42240
#define ATT_SMEM ((42240 + 128) * 4)

__global__ __launch_bounds__(256, 1)
void attn2_kernel(const float* __restrict__ Q, const float* __restrict__ K,
                  const float* __restrict__ V, const int* __restrict__ mask,
                  __nv_bfloat16* __restrict__ Oh, __nv_bfloat16* __restrict__ Ol) {
    extern __shared__ float smf[];
    const int qt = blockIdx.x;
    const int bh = blockIdx.y;
    const int b = bh >> 4, h = bh & 15;
    const int tid = threadIdx.x;
    const int ty = tid >> 4, tx = tid & 15;       // QK map: 8q x 8k
    const int qy = tid >> 3, dx = tid & 7;        // PV map: 4q x 8d
    int* msp = (int*)&smf[ATT_MS];

    const float* Qb = Q + ((size_t)bh * SEQ + qt * 128) * DK;
    const float* Kb = K + (size_t)bh * SEQ * DK;
    const float* Vb = V + (size_t)bh * SEQ * DK;

    for (int idx = tid; idx < 128 * 16; idx += 256) {
        int r = idx >> 4, j = idx & 15;
        float4 v = ((const float4*)Qb)[r * 16 + j];
        float* d = &smf[ATT_QS + r * 65 + j * 4];
        d[0] = v.x; d[1] = v.y; d[2] = v.z; d[3] = v.w;
    }
    if (tid < 128) { smf[ATT_RM + tid] = -1e30f; smf[ATT_RL + tid] = 0.f; }

    float O[4][8];
#pragma unroll
    for (int i = 0; i < 4; i++)
#pragma unroll
        for (int j = 0; j < 8; j++) O[i][j] = 0.f;

    for (int kc = 0; kc < SEQ / 128; kc++) {
        const int k0 = kc * 128;
        __syncthreads();
        for (int idx = tid; idx < 128 * 16; idx += 256) {
            int r = idx >> 4, j = idx & 15;
            float4 kv = ((const float4*)Kb)[(k0 + r) * 16 + j];
            float4 vv = ((const float4*)Vb)[(k0 + r) * 16 + j];
            float* dk = &smf[ATT_KS + r * 65 + j * 4];
            dk[0] = kv.x; dk[1] = kv.y; dk[2] = kv.z; dk[3] = kv.w;
            float* dv = &smf[ATT_VS + r * 68 + j * 4];
            dv[0] = vv.x; dv[1] = vv.y; dv[2] = vv.z; dv[3] = vv.w;
        }
        if (tid < 128) msp[tid] = mask[b * SEQ + k0 + tid];
        __syncthreads();

        float s8[8][8];
#pragma unroll
        for (int i = 0; i < 8; i++)
#pragma unroll
            for (int j = 0; j < 8; j++) s8[i][j] = 0.f;
        for (int d = 0; d < 64; d++) {
            float a[8], bb[8];
#pragma unroll
            for (int i = 0; i < 8; i++) a[i] = smf[ATT_QS + (ty * 8 + i) * 65 + d];
#pragma unroll
            for (int j = 0; j < 8; j++) bb[j] = smf[ATT_KS + (tx * 8 + j) * 65 + d];
#pragma unroll
            for (int i = 0; i < 8; i++)
#pragma unroll
                for (int j = 0; j < 8; j++) s8[i][j] += a[i] * bb[j];
        }
#pragma unroll
        for (int i = 0; i < 8; i++) {
            int q = ty * 8 + i;
            float rm = -1e30f;
#pragma unroll
            for (int j = 0; j < 8; j++) {
                s8[i][j] = msp[tx * 8 + j] ? s8[i][j] * 0.125f : -1e30f;
                rm = fmaxf(rm, s8[i][j]);
            }
            rm = fmaxf(rm, __shfl_xor_sync(0xffffffffu, rm, 1));
            rm = fmaxf(rm, __shfl_xor_sync(0xffffffffu, rm, 2));
            rm = fmaxf(rm, __shfl_xor_sync(0xffffffffu, rm, 4));
            rm = fmaxf(rm, __shfl_xor_sync(0xffffffffu, rm, 8));
            float mo = smf[ATT_RM + q];
            float mn = fmaxf(mo, rm);
            float rs = 0.f;
#pragma unroll
            for (int j = 0; j < 8; j++) {
                float p = __expf(s8[i][j] - mn);
                s8[i][j] = p;
                rs += p;
            }
            rs += __shfl_xor_sync(0xffffffffu, rs, 1);
            rs += __shfl_xor_sync(0xffffffffu, rs, 2);
            rs += __shfl_xor_sync(0xffffffffu, rs, 4);
            rs += __shfl_xor_sync(0xffffffffu, rs, 8);
            if (tx == 0) {
                float al = __expf(mo - mn);
                smf[ATT_RA + q] = al;
                smf[ATT_RM + q] = mn;
                smf[ATT_RL + q] = smf[ATT_RL + q] * al + rs;
            }
#pragma unroll
            for (int j = 0; j < 8; j++) smf[ATT_PS + q * 129 + tx * 8 + j] = s8[i][j];
        }
        __syncthreads();

        float alpha[4];
#pragma unroll
        for (int i = 0; i < 4; i++) alpha[i] = smf[ATT_RA + qy * 4 + i];
#pragma unroll
        for (int i = 0; i < 4; i++)
#pragma unroll
            for (int j = 0; j < 8; j++) O[i][j] *= alpha[i];
        for (int k = 0; k < 128; k++) {
            float4 b0 = *(float4*)&smf[ATT_VS + k * 68 + dx * 8];
            float4 b1 = *(float4*)&smf[ATT_VS + k * 68 + dx * 8 + 4];
            float bb[8] = { b0.x, b0.y, b0.z, b0.w, b1.x, b1.y, b1.z, b1.w };
            float a[4];
#pragma unroll
            for (int i = 0; i < 4; i++) a[i] = smf[ATT_PS + (qy * 4 + i) * 129 + k];
#pragma unroll
            for (int i = 0; i < 4; i++)
#pragma unroll
                for (int j = 0; j < 8; j++) O[i][j] += a[i] * bb[j];
        }
    }
    __syncthreads();

#pragma unroll
    for (int i = 0; i < 4; i++) {
        int q = qy * 4 + i;
        float inv = 1.f / smf[ATT_RL + q];
        int sgl = qt * 128 + q;
        size_t base = ((size_t)b * SEQ + sgl) * EMB + h * DK + dx * 8;
#pragma unroll
        for (int j = 0; j < 8; j++) {
            float v = O[i][j] * inv;
            __nv_bfloat16 hv = __float2bfloat16(v);
            Oh[base + j] = hv;
            Ol[base + j] = __float2bfloat16(v - __bfloat162float(hv));
        }
    }
}

// ==================== launch ====================
extern "C" void kernel_launch(void* const* d_in, const int* in_sizes, int n_in,
                              void* d_out, int out_size) {
    const float* x    = (const float*)d_in[0];
    const int*   mask = (const int*)  d_in[1];
    const float* wq   = (const float*)d_in[2];
    const float* wk   = (const float*)d_in[3];
    const float* wv   = (const float*)d_in[4];
    const float* wo   = (const float*)d_in[5];
    const float* ff1w = (const float*)d_in[6];
    const float* ff1b = (const float*)d_in[7];
    const float* ff2w = (const float*)d_in[8];
    const float* ff2b = (const float*)d_in[9];
    const float* ln1a = (const float*)d_in[10];
    const float* ln1b = (const float*)d_in[11];
    const float* ln2a = (const float*)d_in[12];
    const float* ln2b = (const float*)d_in[13];
    float* out = (float*)d_out;

    float *qb, *kb, *vb, *hb;
    __nv_bfloat16 *lnh, *lnl, *ath, *atl, *ffh, *ffl;
    __nv_bfloat16 *wqh, *wql, *wkh, *wkl, *wvh, *wvl, *woh, *wol, *f1h, *f1l, *f2h, *f2l;
    cudaGetSymbolAddress((void**)&qb, g_q);
    cudaGetSymbolAddress((void**)&kb, g_k);
    cudaGetSymbolAddress((void**)&vb, g_v);
    cudaGetSymbolAddress((void**)&hb, g_h);
    cudaGetSymbolAddress((void**)&lnh, g_lnh);
    cudaGetSymbolAddress((void**)&lnl, g_lnl);
    cudaGetSymbolAddress((void**)&ath, g_ath);
    cudaGetSymbolAddress((void**)&atl, g_atl);
    cudaGetSymbolAddress((void**)&ffh, g_ffh);
    cudaGetSymbolAddress((void**)&ffl, g_ffl);
    cudaGetSymbolAddress((void**)&wqh, g_wqh); cudaGetSymbolAddress((void**)&wql, g_wql);
    cudaGetSymbolAddress((void**)&wkh, g_wkh); cudaGetSymbolAddress((void**)&wkl, g_wkl);
    cudaGetSymbolAddress((void**)&wvh, g_wvh); cudaGetSymbolAddress((void**)&wvl, g_wvl);
    cudaGetSymbolAddress((void**)&woh, g_woh); cudaGetSymbolAddress((void**)&wol, g_wol);
    cudaGetSymbolAddress((void**)&f1h, g_f1h); cudaGetSymbolAddress((void**)&f1l, g_f1l);
    cudaGetSymbolAddress((void**)&f2h, g_f2h); cudaGetSymbolAddress((void**)&f2l, g_f2l);

    cudaFuncSetAttribute(mgemm_kernel<EPI_HEADS>,           cudaFuncAttributeMaxDynamicSharedMemorySize, MGEMM_SMEM);
    cudaFuncSetAttribute(mgemm_kernel<EPI_RES>,             cudaFuncAttributeMaxDynamicSharedMemorySize, MGEMM_SMEM);
    cudaFuncSetAttribute(mgemm_kernel<EPI_BIAS_RELU_SPLIT>, cudaFuncAttributeMaxDynamicSharedMemorySize, MGEMM_SMEM);
    cudaFuncSetAttribute(mgemm_kernel<EPI_BIAS_RES>,        cudaFuncAttributeMaxDynamicSharedMemorySize, MGEMM_SMEM);
    cudaFuncSetAttribute(attn2_kernel,                      cudaFuncAttributeMaxDynamicSharedMemorySize, ATT_SMEM);

    dim3 tb(32, 8);
    splitT_kernel<<<dim3(32, 32), tb>>>(wq, wqh, wql, EMB, EMB);
    splitT_kernel<<<dim3(32, 32), tb>>>(wk, wkh, wkl, EMB, EMB);
    splitT_kernel<<<dim3(32, 32), tb>>>(wv, wvh, wvl, EMB, EMB);
    splitT_kernel<<<dim3(32, 32), tb>>>(wo, woh, wol, EMB, EMB);
    splitT_kernel<<<dim3(128, 32), tb>>>(ff1w, f1h, f1l, EMB, HID);
    splitT_kernel<<<dim3(32, 128), tb>>>(ff2w, f2h, f2l, HID, EMB);

    dim3 gP(EMB / 128, ROWS / 128);   // (8,32)
    dim3 gF(HID / 128, ROWS / 128);   // (32,32)

    ln_kernel<<<ROWS, 256>>>(x, lnh, lnl, ln1a, ln1b);
    mgemm_kernel<EPI_HEADS><<<gP, 256, MGEMM_SMEM>>>(lnh, lnl, wqh, wql, EMB, EMB, qb, nullptr, nullptr, nullptr, nullptr);
    mgemm_kernel<EPI_HEADS><<<gP, 256, MGEMM_SMEM>>>(lnh, lnl, wkh, wkl, EMB, EMB, kb, nullptr, nullptr, nullptr, nullptr);
    mgemm_kernel<EPI_HEADS><<<gP, 256, MGEMM_SMEM>>>(lnh, lnl, wvh, wvl, EMB, EMB, vb, nullptr, nullptr, nullptr, nullptr);
    attn2_kernel<<<dim3(SEQ / 128, BATCH * NHEADS), 256, ATT_SMEM>>>(qb, kb, vb, mask, ath, atl);
    mgemm_kernel<EPI_RES><<<gP, 256, MGEMM_SMEM>>>(ath, atl, woh, wol, EMB, EMB, hb, nullptr, x, nullptr, nullptr);
    ln_kernel<<<ROWS, 256>>>(hb, lnh, lnl, ln2a, ln2b);
    mgemm_kernel<EPI_BIAS_RELU_SPLIT><<<gF, 256, MGEMM_SMEM>>>(lnh, lnl, f1h, f1l, EMB, HID, nullptr, ff1b, nullptr, ffh, ffl);
    mgemm_kernel<EPI_BIAS_RES><<<gP, 256, MGEMM_SMEM>>>(ffh, ffl, f2h, f2l, HID, EMB, out, ff2b, hb, nullptr, nullptr);
}

// round 4
// speedup vs baseline: 4.0599x; 1.8661x over previous
#include <cuda_runtime.h>
#include <cuda_bf16.h>
#include <cstdint>

#define EMB   1024
#define HID   4096
#define NHEADS 16
#define DK    64
#define BATCH 2
#define SEQ   2048
#define ROWS  (BATCH*SEQ)        // 4096
#define LNEPS 1e-6f
#define LOG2E 1.442695041f

// ==================== scratch (device globals) ====================
__device__ float          g_h   [ROWS*EMB];
__device__ __nv_bfloat16  g_lnh [ROWS*EMB];
__device__ __nv_bfloat16  g_lnl [ROWS*EMB];
__device__ __nv_bfloat16  g_qkvh[3*ROWS*EMB];   // [sel][bh][s][d]
__device__ __nv_bfloat16  g_qkvl[3*ROWS*EMB];
__device__ __nv_bfloat16  g_ath [ROWS*EMB];
__device__ __nv_bfloat16  g_atl [ROWS*EMB];
__device__ __nv_bfloat16  g_ffh [ROWS*HID];
__device__ __nv_bfloat16  g_ffl [ROWS*HID];
// transposed split weights [N x K]
__device__ __nv_bfloat16  g_wqkvh[3*EMB*EMB], g_wqkvl[3*EMB*EMB];
__device__ __nv_bfloat16  g_woh[EMB*EMB], g_wol[EMB*EMB];
__device__ __nv_bfloat16  g_f1h[EMB*HID], g_f1l[EMB*HID];
__device__ __nv_bfloat16  g_f2h[EMB*HID], g_f2l[EMB*HID];

// ==================== baseline-PTX helpers ====================
__device__ __forceinline__ uint32_t smem_u32(const void* p) {
    uint32_t a;
    asm("{ .reg .u64 t; cvta.to.shared.u64 t, %1; cvt.u32.u64 %0, t; }" : "=r"(a) : "l"(p));
    return a;
}
__device__ __forceinline__ void cpa16(uint32_t dst, const void* src) {
    asm volatile("cp.async.cg.shared.global [%0], [%1], 16;" :: "r"(dst), "l"(src));
}
__device__ __forceinline__ void ldm4(uint32_t* r, uint32_t addr) {
    asm volatile("ldmatrix.sync.aligned.m8n8.x4.shared.b16 {%0,%1,%2,%3}, [%4];"
                 : "=r"(r[0]), "=r"(r[1]), "=r"(r[2]), "=r"(r[3]) : "r"(addr));
}
__device__ __forceinline__ void ldm4t(uint32_t* r, uint32_t addr) {
    asm volatile("ldmatrix.sync.aligned.m8n8.x4.trans.shared.b16 {%0,%1,%2,%3}, [%4];"
                 : "=r"(r[0]), "=r"(r[1]), "=r"(r[2]), "=r"(r[3]) : "r"(addr));
}
__device__ __forceinline__ void mma_bf16(float* d, const uint32_t* a, const uint32_t* b) {
    asm volatile("mma.sync.aligned.m16n8k16.row.col.f32.bf16.bf16.f32 "
                 "{%0,%1,%2,%3}, {%4,%5,%6,%7}, {%8,%9}, {%0,%1,%2,%3};"
                 : "+f"(d[0]), "+f"(d[1]), "+f"(d[2]), "+f"(d[3])
                 : "r"(a[0]), "r"(a[1]), "r"(a[2]), "r"(a[3]), "r"(b[0]), "r"(b[1]));
}
// pack(lo -> lower half, hi -> upper half)
__device__ __forceinline__ uint32_t packbf(float lo, float hi) {
    uint32_t r;
    asm("cvt.rn.bf16x2.f32 %0, %1, %2;" : "=r"(r) : "f"(hi), "f"(lo));
    return r;
}

// ==================== split-transpose: W[K x N] fp32 -> T[N x K] bf16 hi/lo ====================
__global__ void splitT_kernel(const float* __restrict__ W,
                              __nv_bfloat16* __restrict__ Th,
                              __nv_bfloat16* __restrict__ Tl, int K, int N) {
    __shared__ float tile[32][33];
    int n0 = blockIdx.x * 32, k0 = blockIdx.y * 32;
    int tx = threadIdx.x, ty = threadIdx.y;       // 32 x 8
#pragma unroll
    for (int i = 0; i < 32; i += 8)
        tile[ty + i][tx] = W[(size_t)(k0 + ty + i) * N + n0 + tx];
    __syncthreads();
#pragma unroll
    for (int i = 0; i < 32; i += 8) {
        float v = tile[tx][ty + i];
        __nv_bfloat16 h = __float2bfloat16(v);
        float lo = v - __bfloat162float(h);
        size_t o = (size_t)(n0 + ty + i) * K + k0 + tx;
        Th[o] = h;
        Tl[o] = __float2bfloat16(lo);
    }
}

// ==================== LayerNorm -> bf16 hi/lo ====================
__global__ void ln_kernel(const float* __restrict__ x,
                          __nv_bfloat16* __restrict__ yh, __nv_bfloat16* __restrict__ yl,
                          const float* __restrict__ alpha, const float* __restrict__ beta) {
    __shared__ float red[8];
    int row = blockIdx.x;
    int t = threadIdx.x;
    const float* xr = x + (size_t)row * EMB;
    float v[4];
#pragma unroll
    for (int i = 0; i < 4; i++) v[i] = xr[t + 256 * i];
    float s = v[0] + v[1] + v[2] + v[3];
#pragma unroll
    for (int o = 16; o > 0; o >>= 1) s += __shfl_xor_sync(0xffffffffu, s, o);
    if ((t & 31) == 0) red[t >> 5] = s;
    __syncthreads();
    float tot = 0.f;
#pragma unroll
    for (int i = 0; i < 8; i++) tot += red[i];
    float mean = tot * (1.0f / EMB);
    __syncthreads();
    float sq = 0.f;
#pragma unroll
    for (int i = 0; i < 4; i++) { float d = v[i] - mean; sq += d * d; }
#pragma unroll
    for (int o = 16; o > 0; o >>= 1) sq += __shfl_xor_sync(0xffffffffu, sq, o);
    if ((t & 31) == 0) red[t >> 5] = sq;
    __syncthreads();
    float sqt = 0.f;
#pragma unroll
    for (int i = 0; i < 8; i++) sqt += red[i];
    float stdv = sqrtf(sqt * (1.0f / (EMB - 1)));
    float scale = alpha[0] / (stdv + LNEPS);
    float bias = beta[0];
#pragma unroll
    for (int i = 0; i < 4; i++) {
        float y = scale * (v[i] - mean) + bias;
        __nv_bfloat16 h = __float2bfloat16(y);
        size_t o = (size_t)row * EMB + t + 256 * i;
        yh[o] = h;
        yl[o] = __float2bfloat16(y - __bfloat162float(h));
    }
}

// ==================== mma.sync split-bf16 GEMM ====================
enum { EPI_QKV = 1, EPI_RES = 2, EPI_BIAS_RELU_SPLIT = 3, EPI_BIAS_RES = 4 };

#define TSTRIDE   10240            // 128 rows * 80B
#define BUFSTRIDE (4*TSTRIDE)
#define MGEMM_SMEM (2*BUFSTRIDE)   // 81920 B

template <int EPI>
__global__ __launch_bounds__(256, 2)
void mgemm_kernel(const __nv_bfloat16* __restrict__ Ah, const __nv_bfloat16* __restrict__ Al,
                  const __nv_bfloat16* __restrict__ Bh, const __nv_bfloat16* __restrict__ Bl,
                  int K, int N,
                  float* __restrict__ C, const float* __restrict__ bias,
                  const float* __restrict__ res,
                  __nv_bfloat16* __restrict__ Ch, __nv_bfloat16* __restrict__ Cl) {
    extern __shared__ char sm[];
    const int tid = threadIdx.x;
    const int lane = tid & 31, wid = tid >> 5;
    const int wm = wid >> 2, wn = wid & 3;
    const int bx = blockIdx.x, by = blockIdx.y;
    const uint32_t sb = smem_u32(sm);

    const __nv_bfloat16* gm[4] = {
        Ah + (size_t)(by * 128) * K, Al + (size_t)(by * 128) * K,
        Bh + (size_t)(bx * 128) * K, Bl + (size_t)(bx * 128) * K };

    float acc[4][4][4];
#pragma unroll
    for (int i = 0; i < 4; i++)
#pragma unroll
        for (int j = 0; j < 4; j++)
#pragma unroll
            for (int r = 0; r < 4; r++) acc[i][j][r] = 0.f;

    auto load_chunk = [&](int c, int buf) {
        const size_t koff = (size_t)c * 32;
#pragma unroll
        for (int tl = 0; tl < 4; tl++) {
#pragma unroll
            for (int i = 0; i < 2; i++) {
                int id = tid + 256 * i;
                int r = id >> 2, cc = id & 3;
                cpa16(sb + buf * BUFSTRIDE + tl * TSTRIDE + r * 80 + cc * 16,
                      gm[tl] + (size_t)r * K + koff + cc * 8);
            }
        }
    };

    const int nch = K >> 5;
    load_chunk(0, 0);
    asm volatile("cp.async.commit_group;" ::: "memory");

    for (int c = 0; c < nch; c++) {
        if (c + 1 < nch) {
            load_chunk(c + 1, (c + 1) & 1);
            asm volatile("cp.async.commit_group;" ::: "memory");
            asm volatile("cp.async.wait_group 1;" ::: "memory");
        } else {
            asm volatile("cp.async.wait_group 0;" ::: "memory");
        }
        __syncthreads();

        const uint32_t base = sb + (c & 1) * BUFSTRIDE;
        const char* bufc = sm + (c & 1) * BUFSTRIDE;
#pragma unroll
        for (int kk = 0; kk < 2; kk++) {
            const int kb = kk * 32;
            uint32_t ah[4][4], al4[4][4];
            const uint32_t arow = base + ((wm * 64 + (lane & 15)) * 80) + kb + ((lane >> 4) << 4);
#pragma unroll
            for (int mb = 0; mb < 4; mb++) ldm4(ah[mb], arow + mb * 16 * 80);
            uint32_t bh[4][2], bl[4][2];
#pragma unroll
            for (int nb = 0; nb < 4; nb++) {
                const char* p = bufc + 2 * TSTRIDE
                              + (wn * 32 + nb * 8 + (lane >> 2)) * 80 + kb + (lane & 3) * 4;
                bh[nb][0] = *(const uint32_t*)p;
                bh[nb][1] = *(const uint32_t*)(p + 16);
            }
#pragma unroll
            for (int mb = 0; mb < 4; mb++)
#pragma unroll
                for (int nb = 0; nb < 4; nb++) mma_bf16(acc[mb][nb], ah[mb], bh[nb]);
#pragma unroll
            for (int mb = 0; mb < 4; mb++) ldm4(al4[mb], arow + TSTRIDE + mb * 16 * 80);
#pragma unroll
            for (int mb = 0; mb < 4; mb++)
#pragma unroll
                for (int nb = 0; nb < 4; nb++) mma_bf16(acc[mb][nb], al4[mb], bh[nb]);
#pragma unroll
            for (int nb = 0; nb < 4; nb++) {
                const char* p = bufc + 3 * TSTRIDE
                              + (wn * 32 + nb * 8 + (lane >> 2)) * 80 + kb + (lane & 3) * 4;
                bl[nb][0] = *(const uint32_t*)p;
                bl[nb][1] = *(const uint32_t*)(p + 16);
            }
#pragma unroll
            for (int mb = 0; mb < 4; mb++)
#pragma unroll
                for (int nb = 0; nb < 4; nb++) mma_bf16(acc[mb][nb], ah[mb], bl[nb]);
        }
        __syncthreads();
    }

    // ==================== epilogue ====================
    const int g = lane >> 2, cb = (lane & 3) * 2;
#pragma unroll
    for (int mb = 0; mb < 4; mb++) {
#pragma unroll
        for (int hh = 0; hh < 2; hh++) {
            const int row = by * 128 + wm * 64 + mb * 16 + g + hh * 8;
#pragma unroll
            for (int nb = 0; nb < 4; nb++) {
                const int col = bx * 128 + wn * 32 + nb * 8 + cb;
                float v0 = acc[mb][nb][hh * 2 + 0];
                float v1 = acc[mb][nb][hh * 2 + 1];
                if (EPI == EPI_QKV) {
                    // col 0..3071: sel = Q/K/V, output [sel][b,h][s][d] bf16 hi/lo
                    int sel = col >> 10, hc = col & 1023;
                    int h_ = hc >> 6, d_ = hc & (DK - 1);
                    int b_ = row >> 11, s_ = row & (SEQ - 1);
                    size_t dst = (size_t)sel * ROWS * EMB
                               + (((size_t)(b_ * NHEADS + h_)) * SEQ + s_) * DK + d_;
                    __nv_bfloat16 h0 = __float2bfloat16(v0);
                    __nv_bfloat16 h1 = __float2bfloat16(v1);
                    Ch[dst] = h0; Ch[dst + 1] = h1;
                    Cl[dst]     = __float2bfloat16(v0 - __bfloat162float(h0));
                    Cl[dst + 1] = __float2bfloat16(v1 - __bfloat162float(h1));
                } else if (EPI == EPI_RES) {
                    size_t o = (size_t)row * N + col;
                    C[o]     = v0 + res[o];
                    C[o + 1] = v1 + res[o + 1];
                } else if (EPI == EPI_BIAS_RELU_SPLIT) {
                    v0 = fmaxf(v0 + bias[col], 0.f);
                    v1 = fmaxf(v1 + bias[col + 1], 0.f);
                    __nv_bfloat16 h0 = __float2bfloat16(v0);
                    __nv_bfloat16 h1 = __float2bfloat16(v1);
                    size_t o = (size_t)row * N + col;
                    Ch[o] = h0; Ch[o + 1] = h1;
                    Cl[o]     = __float2bfloat16(v0 - __bfloat162float(h0));
                    Cl[o + 1] = __float2bfloat16(v1 - __bfloat162float(h1));
                } else { // EPI_BIAS_RES
                    size_t o = (size_t)row * N + col;
                    C[o]     = v0 + bias[col]     + res[o];
                    C[o + 1] = v1 + bias[col + 1] + res[o + 1];
                }
            }
        }
    }
}

// ==================== tensor-core flash attention ====================
// CTA: 128 q rows, 8 warps x 16 rows. K/V tiles of 128 keys, double-buffered.
// Scores: 3-pass split mma. PV: P hi/lo (in-register frag conversion) x V hi/lo (3 passes).
#define AT_STRIDE 144
#define AT_QH 0
#define AT_QL 18432
#define AT_KV0 36864            // per stage: KH, KL, VH, VL each 18432 (73728/stage, 2 stages)
#define AT_MASK 184320          // 2 x 128 ints
#define ATT_SMEM (184320 + 1024)

__global__ __launch_bounds__(256, 1)
void attn3_kernel(const __nv_bfloat16* __restrict__ QKVh,
                  const __nv_bfloat16* __restrict__ QKVl,
                  const int* __restrict__ mask,
                  __nv_bfloat16* __restrict__ Oh, __nv_bfloat16* __restrict__ Ol) {
    extern __shared__ char sm[];
    const uint32_t sb = smem_u32(sm);
    const int tid = threadIdx.x, lane = tid & 31, w = tid >> 5;
    const int g = lane >> 2, c4 = lane & 3;
    const int qt = blockIdx.x, bh = blockIdx.y;
    const int b = bh >> 4, h = bh & 15;

    const __nv_bfloat16* Qh = QKVh;
    const __nv_bfloat16* Ql = QKVl;
    const __nv_bfloat16* Kh = QKVh + (size_t)ROWS * EMB;
    const __nv_bfloat16* Kl = QKVl + (size_t)ROWS * EMB;
    const __nv_bfloat16* Vh = QKVh + 2 * (size_t)ROWS * EMB;
    const __nv_bfloat16* Vl = QKVl + 2 * (size_t)ROWS * EMB;

    const size_t qoff = ((size_t)bh * SEQ + qt * 128) * DK;
    const size_t kvbase = (size_t)bh * SEQ * DK;

    // Q hi/lo -> smem
#pragma unroll
    for (int mtx = 0; mtx < 2; mtx++) {
        const __nv_bfloat16* src = mtx ? Ql : Qh;
#pragma unroll
        for (int i = 0; i < 4; i++) {
            int id = tid + 256 * i;
            int r = id >> 3, cc = id & 7;
            cpa16(sb + AT_QH + mtx * 18432 + r * AT_STRIDE + cc * 16,
                  src + qoff + (size_t)r * DK + cc * 8);
        }
    }
    auto load_kv = [&](int kc, int stg) {
        const size_t koff = kvbase + (size_t)kc * 128 * DK;
        const __nv_bfloat16* srcs[4] = { Kh + koff, Kl + koff, Vh + koff, Vl + koff };
#pragma unroll
        for (int mtx = 0; mtx < 4; mtx++) {
#pragma unroll
            for (int i = 0; i < 4; i++) {
                int id = tid + 256 * i;
                int r = id >> 3, cc = id & 7;
                cpa16(sb + AT_KV0 + stg * 73728 + mtx * 18432 + r * AT_STRIDE + cc * 16,
                      srcs[mtx] + (size_t)r * DK + cc * 8);
            }
        }
        if (tid < 32)
            cpa16(sb + AT_MASK + stg * 512 + tid * 16, mask + b * SEQ + kc * 128 + tid * 4);
    };
    load_kv(0, 0);
    asm volatile("cp.async.commit_group;" ::: "memory");
    load_kv(1, 1);
    asm volatile("cp.async.commit_group;" ::: "memory");
    asm volatile("cp.async.wait_group 1;" ::: "memory");
    __syncthreads();

    // hoist Q fragments (4 k16 steps, hi+lo)
    uint32_t qfh[4][4], qfl[4][4];
    {
        const uint32_t qrow = sb + AT_QH + (w * 16 + (lane & 15)) * AT_STRIDE + ((lane >> 4) << 4);
#pragma unroll
        for (int ks = 0; ks < 4; ks++) {
            ldm4(qfh[ks], qrow + ks * 32);
            ldm4(qfl[ks], qrow + 18432 + ks * 32);
        }
    }

    float accO[8][4];
#pragma unroll
    for (int i = 0; i < 8; i++)
#pragma unroll
        for (int j = 0; j < 4; j++) accO[i][j] = 0.f;
    float m0 = -1e30f, m1 = -1e30f, l0 = 0.f, l1 = 0.f;

    for (int kc = 0; kc < SEQ / 128; kc++) {
        if (kc >= 1 && kc + 1 < SEQ / 128) {
            load_kv(kc + 1, (kc + 1) & 1);
            asm volatile("cp.async.commit_group;" ::: "memory");
            asm volatile("cp.async.wait_group 1;" ::: "memory");
            __syncthreads();
        } else if (kc + 1 == SEQ / 128) {
            asm volatile("cp.async.wait_group 0;" ::: "memory");
            __syncthreads();
        }
        const uint32_t kvb = sb + AT_KV0 + (kc & 1) * 73728;
        const int* msp = (const int*)(sm + AT_MASK + (kc & 1) * 512);

        // ---- QK^T: 16 n8 blocks ----
        float s[16][4];
#pragma unroll
        for (int nb = 0; nb < 16; nb++)
#pragma unroll
            for (int j = 0; j < 4; j++) s[nb][j] = 0.f;
#pragma unroll
        for (int ks = 0; ks < 4; ks++) {
#pragma unroll
            for (int np = 0; np < 8; np++) {
                const int grp = lane >> 3;
                const uint32_t baddr = kvb + (np * 16 + (grp >> 1) * 8 + (lane & 7)) * AT_STRIDE
                                     + ks * 32 + (grp & 1) * 16;
                uint32_t bfh[4], bfl[4];
                ldm4(bfh, baddr);
                ldm4(bfl, baddr + 18432);
                mma_bf16(s[np * 2 + 0], qfh[ks], bfh + 0);
                mma_bf16(s[np * 2 + 0], qfl[ks], bfh + 0);
                mma_bf16(s[np * 2 + 0], qfh[ks], bfl + 0);
                mma_bf16(s[np * 2 + 1], qfh[ks], bfh + 2);
                mma_bf16(s[np * 2 + 1], qfl[ks], bfh + 2);
                mma_bf16(s[np * 2 + 1], qfh[ks], bfl + 2);
            }
        }

        // ---- scale + mask + online softmax ----
        float rm0 = -1e30f, rm1 = -1e30f;
#pragma unroll
        for (int nb = 0; nb < 16; nb++) {
            const int col = nb * 8 + c4 * 2;
            const bool ok0 = msp[col] != 0, ok1 = msp[col + 1] != 0;
            s[nb][0] = ok0 ? s[nb][0] * 0.125f : -1e30f;
            s[nb][1] = ok1 ? s[nb][1] * 0.125f : -1e30f;
            s[nb][2] = ok0 ? s[nb][2] * 0.125f : -1e30f;
            s[nb][3] = ok1 ? s[nb][3] * 0.125f : -1e30f;
            rm0 = fmaxf(rm0, fmaxf(s[nb][0], s[nb][1]));
            rm1 = fmaxf(rm1, fmaxf(s[nb][2], s[nb][3]));
        }
        rm0 = fmaxf(rm0, __shfl_xor_sync(0xffffffffu, rm0, 1));
        rm0 = fmaxf(rm0, __shfl_xor_sync(0xffffffffu, rm0, 2));
        rm1 = fmaxf(rm1, __shfl_xor_sync(0xffffffffu, rm1, 1));
        rm1 = fmaxf(rm1, __shfl_xor_sync(0xffffffffu, rm1, 2));
        const float mn0 = fmaxf(m0, rm0), mn1 = fmaxf(m1, rm1);
        const float al0 = exp2f((m0 - mn0) * LOG2E);
        const float al1 = exp2f((m1 - mn1) * LOG2E);
        m0 = mn0; m1 = mn1;
        float rs0 = 0.f, rs1 = 0.f;
#pragma unroll
        for (int nb = 0; nb < 16; nb++) {
            s[nb][0] = exp2f((s[nb][0] - mn0) * LOG2E);
            s[nb][1] = exp2f((s[nb][1] - mn0) * LOG2E);
            s[nb][2] = exp2f((s[nb][2] - mn1) * LOG2E);
            s[nb][3] = exp2f((s[nb][3] - mn1) * LOG2E);
            rs0 += s[nb][0] + s[nb][1];
            rs1 += s[nb][2] + s[nb][3];
        }
        rs0 += __shfl_xor_sync(0xffffffffu, rs0, 1);
        rs0 += __shfl_xor_sync(0xffffffffu, rs0, 2);
        rs1 += __shfl_xor_sync(0xffffffffu, rs1, 1);
        rs1 += __shfl_xor_sync(0xffffffffu, rs1, 2);
        l0 = l0 * al0 + rs0;
        l1 = l1 * al1 + rs1;
#pragma unroll
        for (int dnb = 0; dnb < 8; dnb++) {
            accO[dnb][0] *= al0; accO[dnb][1] *= al0;
            accO[dnb][2] *= al1; accO[dnb][3] *= al1;
        }

        // ---- PV: 8 k16 steps over 128 keys ----
#pragma unroll
        for (int ks = 0; ks < 8; ks++) {
            // P fragments from score regs (C-frag == A-frag layout identity)
            float e[8] = { s[2*ks][0], s[2*ks][1], s[2*ks][2], s[2*ks][3],
                           s[2*ks+1][0], s[2*ks+1][1], s[2*ks+1][2], s[2*ks+1][3] };
            float eh[8], el[8];
#pragma unroll
            for (int i = 0; i < 8; i++) {
                __nv_bfloat16 hb = __float2bfloat16(e[i]);
                eh[i] = __bfloat162float(hb);
                el[i] = e[i] - eh[i];
            }
            uint32_t pah[4] = { packbf(eh[0], eh[1]), packbf(eh[2], eh[3]),
                                packbf(eh[4], eh[5]), packbf(eh[6], eh[7]) };
            uint32_t pal[4] = { packbf(el[0], el[1]), packbf(el[2], el[3]),
                                packbf(el[4], el[5]), packbf(el[6], el[7]) };
#pragma unroll
            for (int dp = 0; dp < 4; dp++) {
                const int grp = lane >> 3;
                const uint32_t vaddr = kvb + 36864
                                     + (ks * 16 + (grp & 1) * 8 + (lane & 7)) * AT_STRIDE
                                     + dp * 32 + (grp >> 1) * 16;
                uint32_t vfh[4], vfl[4];
                ldm4t(vfh, vaddr);
                ldm4t(vfl, vaddr + 18432);
                mma_bf16(accO[dp * 2 + 0], pah, vfh + 0);
                mma_bf16(accO[dp * 2 + 0], pal, vfh + 0);
                mma_bf16(accO[dp * 2 + 0], pah, vfl + 0);
                mma_bf16(accO[dp * 2 + 1], pah, vfh + 2);
                mma_bf16(accO[dp * 2 + 1], pal, vfh + 2);
                mma_bf16(accO[dp * 2 + 1], pah, vfl + 2);
            }
        }
        if (kc + 1 < SEQ / 128) __syncthreads();   // protect smem stage before next overwrite
    }

    // ---- normalize + write bf16 hi/lo ----
    const float inv0 = 1.f / l0, inv1 = 1.f / l1;
    const int s0 = qt * 128 + w * 16 + g;
    const size_t r0 = ((size_t)b * SEQ + s0) * EMB + h * DK;
    const size_t r1 = ((size_t)b * SEQ + s0 + 8) * EMB + h * DK;
#pragma unroll
    for (int dnb = 0; dnb < 8; dnb++) {
        const int col = dnb * 8 + c4 * 2;
        float v0 = accO[dnb][0] * inv0, v1 = accO[dnb][1] * inv0;
        float v2 = accO[dnb][2] * inv1, v3 = accO[dnb][3] * inv1;
        __nv_bfloat16 h0 = __float2bfloat16(v0), h1 = __float2bfloat16(v1);
        __nv_bfloat16 h2 = __float2bfloat16(v2), h3 = __float2bfloat16(v3);
        *(uint32_t*)(Oh + r0 + col) = packbf(__bfloat162float(h0) == 0.f && false ? 0.f : v0, v1) ;
        // NOTE: direct pack of rounded values:
        *(uint32_t*)(Oh + r0 + col) = ((uint32_t)__bfloat16_as_ushort(h1) << 16) | __bfloat16_as_ushort(h0);
        *(uint32_t*)(Oh + r1 + col) = ((uint32_t)__bfloat16_as_ushort(h3) << 16) | __bfloat16_as_ushort(h2);
        __nv_bfloat16 q0 = __float2bfloat16(v0 - __bfloat162float(h0));
        __nv_bfloat16 q1 = __float2bfloat16(v1 - __bfloat162float(h1));
        __nv_bfloat16 q2 = __float2bfloat16(v2 - __bfloat162float(h2));
        __nv_bfloat16 q3 = __float2bfloat16(v3 - __bfloat162float(h3));
        *(uint32_t*)(Ol + r0 + col) = ((uint32_t)__bfloat16_as_ushort(q1) << 16) | __bfloat16_as_ushort(q0);
        *(uint32_t*)(Ol + r1 + col) = ((uint32_t)__bfloat16_as_ushort(q3) << 16) | __bfloat16_as_ushort(q2);
    }
}

// ==================== launch ====================
extern "C" void kernel_launch(void* const* d_in, const int* in_sizes, int n_in,
                              void* d_out, int out_size) {
    const float* x    = (const float*)d_in[0];
    const int*   mask = (const int*)  d_in[1];
    const float* wq   = (const float*)d_in[2];
    const float* wk   = (const float*)d_in[3];
    const float* wv   = (const float*)d_in[4];
    const float* wo   = (const float*)d_in[5];
    const float* ff1w = (const float*)d_in[6];
    const float* ff1b = (const float*)d_in[7];
    const float* ff2w = (const float*)d_in[8];
    const float* ff2b = (const float*)d_in[9];
    const float* ln1a = (const float*)d_in[10];
    const float* ln1b = (const float*)d_in[11];
    const float* ln2a = (const float*)d_in[12];
    const float* ln2b = (const float*)d_in[13];
    float* out = (float*)d_out;

    float *hb;
    __nv_bfloat16 *lnh, *lnl, *qkvh, *qkvl, *ath, *atl, *ffh, *ffl;
    __nv_bfloat16 *wqkvh, *wqkvl, *woh, *wol, *f1h, *f1l, *f2h, *f2l;
    cudaGetSymbolAddress((void**)&hb, g_h);
    cudaGetSymbolAddress((void**)&lnh, g_lnh);
    cudaGetSymbolAddress((void**)&lnl, g_lnl);
    cudaGetSymbolAddress((void**)&qkvh, g_qkvh);
    cudaGetSymbolAddress((void**)&qkvl, g_qkvl);
    cudaGetSymbolAddress((void**)&ath, g_ath);
    cudaGetSymbolAddress((void**)&atl, g_atl);
    cudaGetSymbolAddress((void**)&ffh, g_ffh);
    cudaGetSymbolAddress((void**)&ffl, g_ffl);
    cudaGetSymbolAddress((void**)&wqkvh, g_wqkvh);
    cudaGetSymbolAddress((void**)&wqkvl, g_wqkvl);
    cudaGetSymbolAddress((void**)&woh, g_woh); cudaGetSymbolAddress((void**)&wol, g_wol);
    cudaGetSymbolAddress((void**)&f1h, g_f1h); cudaGetSymbolAddress((void**)&f1l, g_f1l);
    cudaGetSymbolAddress((void**)&f2h, g_f2h); cudaGetSymbolAddress((void**)&f2l, g_f2l);

    cudaFuncSetAttribute(mgemm_kernel<EPI_QKV>,             cudaFuncAttributeMaxDynamicSharedMemorySize, MGEMM_SMEM);
    cudaFuncSetAttribute(mgemm_kernel<EPI_RES>,             cudaFuncAttributeMaxDynamicSharedMemorySize, MGEMM_SMEM);
    cudaFuncSetAttribute(mgemm_kernel<EPI_BIAS_RELU_SPLIT>, cudaFuncAttributeMaxDynamicSharedMemorySize, MGEMM_SMEM);
    cudaFuncSetAttribute(mgemm_kernel<EPI_BIAS_RES>,        cudaFuncAttributeMaxDynamicSharedMemorySize, MGEMM_SMEM);
    cudaFuncSetAttribute(attn3_kernel,                      cudaFuncAttributeMaxDynamicSharedMemorySize, ATT_SMEM);

    dim3 tb(32, 8);
    // weight split-transposes; QKV concatenated [3072 x 1024]
    splitT_kernel<<<dim3(32, 32), tb>>>(wq, wqkvh + 0*EMB*EMB, wqkvl + 0*EMB*EMB, EMB, EMB);
    splitT_kernel<<<dim3(32, 32), tb>>>(wk, wqkvh + 1*EMB*EMB, wqkvl + 1*EMB*EMB, EMB, EMB);
    splitT_kernel<<<dim3(32, 32), tb>>>(wv, wqkvh + 2*EMB*EMB, wqkvl + 2*EMB*EMB, EMB, EMB);
    splitT_kernel<<<dim3(32, 32), tb>>>(wo, woh, wol, EMB, EMB);
    splitT_kernel<<<dim3(128, 32), tb>>>(ff1w, f1h, f1l, EMB, HID);
    splitT_kernel<<<dim3(32, 128), tb>>>(ff2w, f2h, f2l, HID, EMB);

    dim3 gQKV(3 * EMB / 128, ROWS / 128); // (24,32)
    dim3 gP(EMB / 128, ROWS / 128);       // (8,32)
    dim3 gF(HID / 128, ROWS / 128);       // (32,32)

    ln_kernel<<<ROWS, 256>>>(x, lnh, lnl, ln1a, ln1b);
    mgemm_kernel<EPI_QKV><<<gQKV, 256, MGEMM_SMEM>>>(lnh, lnl, wqkvh, wqkvl, EMB, 3*EMB, nullptr, nullptr, nullptr, qkvh, qkvl);
    attn3_kernel<<<dim3(SEQ / 128, BATCH * NHEADS), 256, ATT_SMEM>>>(qkvh, qkvl, mask, ath, atl);
    mgemm_kernel<EPI_RES><<<gP, 256, MGEMM_SMEM>>>(ath, atl, woh, wol, EMB, EMB, hb, nullptr, x, nullptr, nullptr);
    ln_kernel<<<ROWS, 256>>>(hb, lnh, lnl, ln2a, ln2b);
    mgemm_kernel<EPI_BIAS_RELU_SPLIT><<<gF, 256, MGEMM_SMEM>>>(lnh, lnl, f1h, f1l, EMB, HID, nullptr, ff1b, nullptr, ffh, ffl);
    mgemm_kernel<EPI_BIAS_RES><<<gP, 256, MGEMM_SMEM>>>(ffh, ffl, f2h, f2l, HID, EMB, out, ff2b, hb, nullptr, nullptr);
}